// round 3
// baseline (speedup 1.0000x reference)
#include <cuda_runtime.h>
#include <math.h>
#include <stdint.h>

#define BATCH  4
#define LSEQ   4096
#define CDIM   512
#define GROUPS 32
#define CPG    16          // channels per group
#define EPS_GN 1e-6f

// ---------------------------------------------------------------------------
// Scratch (static device globals — allocation-free per harness rules)
// ---------------------------------------------------------------------------
static __device__ float g_xn [(size_t)BATCH*LSEQ*CDIM];   // 32 MB
static __device__ float g_q  [(size_t)BATCH*LSEQ*CDIM];
static __device__ float g_k  [(size_t)BATCH*LSEQ*CDIM];
static __device__ float g_v  [(size_t)BATCH*LSEQ*CDIM];
static __device__ float g_ctx[(size_t)BATCH*LSEQ*CDIM];
static __device__ float g_s  [(size_t)BATCH*LSEQ*LSEQ];   // 256 MB scores
static __device__ float g_mean[BATCH*GROUPS];
static __device__ float g_rstd[BATCH*GROUPS];

// Buffer selector so host code never needs device-symbol addresses.
__device__ __forceinline__ float* buf_sel(int sel, const void* ext) {
    switch (sel) {
        case 0: return g_xn;
        case 1: return g_q;
        case 2: return g_k;
        case 3: return g_v;
        case 4: return g_s;
        case 5: return g_ctx;
        default: return (float*)ext;
    }
}

// ---------------------------------------------------------------------------
// GroupNorm statistics: one block per (batch, group); reduce 4096*16 elements
// ---------------------------------------------------------------------------
__global__ void __launch_bounds__(256) gn_stats_kernel(const float* __restrict__ x) {
    int b = blockIdx.x / GROUPS;
    int g = blockIdx.x % GROUPS;
    const float* base = x + (size_t)b * LSEQ * CDIM + g * CPG;
    float s = 0.f, s2 = 0.f;
    for (int l = threadIdx.x; l < LSEQ; l += 256) {
        const float4* p = (const float4*)(base + (size_t)l * CDIM);
        #pragma unroll
        for (int j = 0; j < CPG / 4; ++j) {
            float4 v = p[j];
            s  += v.x + v.y + v.z + v.w;
            s2 += v.x*v.x + v.y*v.y + v.z*v.z + v.w*v.w;
        }
    }
    __shared__ float sh1[256], sh2[256];
    sh1[threadIdx.x] = s; sh2[threadIdx.x] = s2;
    __syncthreads();
    for (int st = 128; st > 0; st >>= 1) {
        if (threadIdx.x < st) {
            sh1[threadIdx.x] += sh1[threadIdx.x + st];
            sh2[threadIdx.x] += sh2[threadIdx.x + st];
        }
        __syncthreads();
    }
    if (threadIdx.x == 0) {
        const float inv = 1.f / (float)(LSEQ * CPG);
        float m   = sh1[0] * inv;
        float var = sh2[0] * inv - m * m;
        g_mean[blockIdx.x] = m;
        g_rstd[blockIdx.x] = rsqrtf(var + EPS_GN);
    }
}

// ---------------------------------------------------------------------------
// Normalize + affine -> g_xn  (float4 elementwise, 8192 blocks x 256)
// ---------------------------------------------------------------------------
__global__ void __launch_bounds__(256) gn_norm_kernel(const float* __restrict__ x,
                                                      const float* __restrict__ w,
                                                      const float* __restrict__ bb) {
    size_t idx4 = (size_t)blockIdx.x * 256 + threadIdx.x;
    size_t i = idx4 * 4;
    int c = (int)(i & (CDIM - 1));
    size_t bl = i >> 9;               // / CDIM
    int b = (int)(bl >> 12);          // / LSEQ
    int gidx = b * GROUPS + (c >> 4);
    float m = g_mean[gidx], r = g_rstd[gidx];
    float4 v  = *(const float4*)(x + i);
    float4 gw = *(const float4*)(w + c);
    float4 gb = *(const float4*)(bb + c);
    float4 o;
    o.x = (v.x - m) * r * gw.x + gb.x;
    o.y = (v.y - m) * r * gw.y + gb.y;
    o.z = (v.z - m) * r * gw.z + gb.z;
    o.w = (v.w - m) * r * gw.w + gb.w;
    *(float4*)(g_xn + i) = o;
}

// ---------------------------------------------------------------------------
// Tiled fp32 GEMM: C[M,N] = alpha * A[M,K] @ (B or B^T) (+bias[n]) (+resid)
// BM=BN=128, BK=8, 256 threads, 8x8 accum per thread. blockIdx.z = batch.
// TRANSB: B stored [N,K] (used for Q @ K^T).
// ---------------------------------------------------------------------------
template<bool TRANSB, bool BIAS, bool RESID>
__global__ void __launch_bounds__(256) gemm_kernel(
    int aSel, const float* __restrict__ aExt,
    int bSel, const float* __restrict__ bExt,
    int cSel, float* __restrict__ cExt,
    int M, int N, int Kd,
    size_t sA, size_t sB, size_t sC,
    float alpha,
    const float* __restrict__ bias,
    const float* __restrict__ resid)
{
    const float* A  = buf_sel(aSel, aExt) + (size_t)blockIdx.z * sA;
    const float* Bm = buf_sel(bSel, bExt) + (size_t)blockIdx.z * sB;
    float*       Cm = buf_sel(cSel, cExt) + (size_t)blockIdx.z * sC;

    const int tid  = threadIdx.x;
    const int row0 = blockIdx.y * 128;
    const int col0 = blockIdx.x * 128;
    const int tm0  = (tid >> 4) << 3;   // 0..120
    const int tn0  = (tid & 15) << 3;   // 0..120

    __shared__ float As[8][128];
    __shared__ float Bs[8][128];

    float acc[8][8];
    #pragma unroll
    for (int i = 0; i < 8; ++i)
        #pragma unroll
        for (int j = 0; j < 8; ++j) acc[i][j] = 0.f;

    const int am = tid >> 1;            // 0..127
    const int ak = (tid & 1) << 2;      // 0 or 4

    for (int kk = 0; kk < Kd; kk += 8) {
        // A tile 128x8 (store transposed)
        {
            float4 av = *(const float4*)(A + (size_t)(row0 + am) * Kd + kk + ak);
            As[ak + 0][am] = av.x;
            As[ak + 1][am] = av.y;
            As[ak + 2][am] = av.z;
            As[ak + 3][am] = av.w;
        }
        // B tile 8x128
        if (!TRANSB) {
            int bk = tid >> 5;               // 0..7
            int bn = (tid & 31) << 2;        // 0..124
            float4 bv = *(const float4*)(Bm + (size_t)(kk + bk) * N + col0 + bn);
            *(float4*)(&Bs[bk][bn]) = bv;
        } else {
            int bn = tid >> 1;               // 0..127
            int bk = (tid & 1) << 2;         // 0 or 4
            float4 bv = *(const float4*)(Bm + (size_t)(col0 + bn) * Kd + kk + bk);
            Bs[bk + 0][bn] = bv.x;
            Bs[bk + 1][bn] = bv.y;
            Bs[bk + 2][bn] = bv.z;
            Bs[bk + 3][bn] = bv.w;
        }
        __syncthreads();

        #pragma unroll
        for (int k = 0; k < 8; ++k) {
            float a[8], b[8];
            float4 a0 = *(float4*)(&As[k][tm0]);
            float4 a1 = *(float4*)(&As[k][tm0 + 4]);
            float4 b0 = *(float4*)(&Bs[k][tn0]);
            float4 b1 = *(float4*)(&Bs[k][tn0 + 4]);
            a[0]=a0.x; a[1]=a0.y; a[2]=a0.z; a[3]=a0.w;
            a[4]=a1.x; a[5]=a1.y; a[6]=a1.z; a[7]=a1.w;
            b[0]=b0.x; b[1]=b0.y; b[2]=b0.z; b[3]=b0.w;
            b[4]=b1.x; b[5]=b1.y; b[6]=b1.z; b[7]=b1.w;
            #pragma unroll
            for (int i = 0; i < 8; ++i)
                #pragma unroll
                for (int j = 0; j < 8; ++j)
                    acc[i][j] = fmaf(a[i], b[j], acc[i][j]);
        }
        __syncthreads();
    }

    // Epilogue
    float bias_v[8];
    if (BIAS) {
        #pragma unroll
        for (int j = 0; j < 8; ++j) bias_v[j] = bias[col0 + tn0 + j];
    }
    const int c0 = col0 + tn0;
    #pragma unroll
    for (int i = 0; i < 8; ++i) {
        size_t r = (size_t)(row0 + tm0 + i);
        float4 v0, v1;
        v0.x = acc[i][0] * alpha; v0.y = acc[i][1] * alpha;
        v0.z = acc[i][2] * alpha; v0.w = acc[i][3] * alpha;
        v1.x = acc[i][4] * alpha; v1.y = acc[i][5] * alpha;
        v1.z = acc[i][6] * alpha; v1.w = acc[i][7] * alpha;
        if (BIAS) {
            v0.x += bias_v[0]; v0.y += bias_v[1]; v0.z += bias_v[2]; v0.w += bias_v[3];
            v1.x += bias_v[4]; v1.y += bias_v[5]; v1.z += bias_v[6]; v1.w += bias_v[7];
        }
        if (RESID) {
            float4 r0 = *(const float4*)(resid + r * N + c0);
            float4 r1 = *(const float4*)(resid + r * N + c0 + 4);
            v0.x += r0.x; v0.y += r0.y; v0.z += r0.z; v0.w += r0.w;
            v1.x += r1.x; v1.y += r1.y; v1.z += r1.z; v1.w += r1.w;
        }
        *(float4*)(Cm + r * N + c0)     = v0;
        *(float4*)(Cm + r * N + c0 + 4) = v1;
    }
}

// ---------------------------------------------------------------------------
// Row softmax over g_s (in place). One block per row of length 4096.
// ---------------------------------------------------------------------------
__global__ void __launch_bounds__(256) softmax_kernel() {
    float* row = g_s + (size_t)blockIdx.x * LSEQ;
    int t = threadIdx.x;
    float v[16];
    float m = -1e30f;
    #pragma unroll
    for (int j = 0; j < 16; ++j) {
        v[j] = row[t + j * 256];
        m = fmaxf(m, v[j]);
    }
    __shared__ float sh[256];
    sh[t] = m; __syncthreads();
    for (int st = 128; st > 0; st >>= 1) {
        if (t < st) sh[t] = fmaxf(sh[t], sh[t + st]);
        __syncthreads();
    }
    m = sh[0];
    __syncthreads();
    float s = 0.f;
    #pragma unroll
    for (int j = 0; j < 16; ++j) {
        v[j] = __expf(v[j] - m);
        s += v[j];
    }
    sh[t] = s; __syncthreads();
    for (int st = 128; st > 0; st >>= 1) {
        if (t < st) sh[t] += sh[t + st];
        __syncthreads();
    }
    float inv = 1.f / sh[0];
    #pragma unroll
    for (int j = 0; j < 16; ++j) row[t + j * 256] = v[j] * inv;
}

// ---------------------------------------------------------------------------
// Launch
// ---------------------------------------------------------------------------
extern "C" void kernel_launch(void* const* d_in, const int* in_sizes, int n_in,
                              void* d_out, int out_size) {
    const float* x   = (const float*)d_in[0];
    const float* gnw = (const float*)d_in[1];
    const float* gnb = (const float*)d_in[2];
    const float* wq  = (const float*)d_in[3];
    const float* bq  = (const float*)d_in[4];
    const float* wk  = (const float*)d_in[5];
    const float* bk  = (const float*)d_in[6];
    const float* wv  = (const float*)d_in[7];
    const float* bv  = (const float*)d_in[8];
    const float* wo  = (const float*)d_in[9];
    const float* bo  = (const float*)d_in[10];
    float* out = (float*)d_out;

    const size_t LC  = (size_t)LSEQ * CDIM;   // per-batch q/k/v stride
    const size_t LL  = (size_t)LSEQ * LSEQ;   // per-batch scores stride
    const float  attn_scale = 1.f / sqrtf((float)CDIM);

    // 1) GroupNorm
    gn_stats_kernel<<<BATCH * GROUPS, 256>>>(x);
    gn_norm_kernel<<<(BATCH * LSEQ * CDIM / 4) / 256, 256>>>(x, gnw, gnb);

    // 2) QKV projections: [16384,512] @ [512,512] + bias
    dim3 grid_qkv(CDIM / 128, (BATCH * LSEQ) / 128, 1);
    gemm_kernel<false, true, false><<<grid_qkv, 256>>>(
        0, nullptr, -1, wq, 1, nullptr, BATCH * LSEQ, CDIM, CDIM, 0, 0, 0, 1.f, bq, nullptr);
    gemm_kernel<false, true, false><<<grid_qkv, 256>>>(
        0, nullptr, -1, wk, 2, nullptr, BATCH * LSEQ, CDIM, CDIM, 0, 0, 0, 1.f, bk, nullptr);
    gemm_kernel<false, true, false><<<grid_qkv, 256>>>(
        0, nullptr, -1, wv, 3, nullptr, BATCH * LSEQ, CDIM, CDIM, 0, 0, 0, 1.f, bv, nullptr);

    // 3) scores = scale * Q @ K^T  (batched via blockIdx.z)
    dim3 grid_s(LSEQ / 128, LSEQ / 128, BATCH);
    gemm_kernel<true, false, false><<<grid_s, 256>>>(
        1, nullptr, 2, nullptr, 4, nullptr, LSEQ, LSEQ, CDIM, LC, LC, LL,
        attn_scale, nullptr, nullptr);

    // 4) softmax rows
    softmax_kernel<<<BATCH * LSEQ, 256>>>();

    // 5) ctx = P @ V (batched)
    dim3 grid_pv(CDIM / 128, LSEQ / 128, BATCH);
    gemm_kernel<false, false, false><<<grid_pv, 256>>>(
        4, nullptr, 3, nullptr, 5, nullptr, LSEQ, CDIM, LSEQ, LL, LC, LC,
        1.f, nullptr, nullptr);

    // 6) out = ctx @ wo + bo + residual
    gemm_kernel<false, true, true><<<grid_qkv, 256>>>(
        5, nullptr, -1, wo, -1, out, BATCH * LSEQ, CDIM, CDIM, 0, 0, 0,
        1.f, bo, x);
}

// round 5
// speedup vs baseline: 2.3306x; 2.3306x over previous
#include <cuda_runtime.h>
#include <cuda_bf16.h>
#include <math.h>
#include <stdint.h>

#define BATCH  4
#define LSEQ   4096
#define CDIM   512
#define BLTOT  (BATCH*LSEQ)
#define GROUPS 32
#define EPS_GN 1e-6f

// ---- mma.sync GEMM tiling ----
#define BM 128
#define BN 128
#define BK 32
#define ROWB   80                    // SMEM row stride bytes (32 bf16 + 8 skew)
#define TILE_B (128*ROWB)            // 10240 B per operand tile
#define STAGE_B (4*TILE_B)           // Ahi,Alo,Bhi,Blo = 40960 B
#define NSTAGE 3
#define SMEM_TOTAL (NSTAGE*STAGE_B)  // 122880 B

// ---------------------------------------------------------------------------
// Scratch (static device globals)
// ---------------------------------------------------------------------------
#define DEVBUF static __device__ __align__(16)
DEVBUF __nv_bfloat16 g_xn_hi [(size_t)BLTOT*CDIM];
DEVBUF __nv_bfloat16 g_xn_lo [(size_t)BLTOT*CDIM];
DEVBUF __nv_bfloat16 g_q_hi  [(size_t)BLTOT*CDIM];
DEVBUF __nv_bfloat16 g_q_lo  [(size_t)BLTOT*CDIM];
DEVBUF __nv_bfloat16 g_k_hi  [(size_t)BLTOT*CDIM];
DEVBUF __nv_bfloat16 g_k_lo  [(size_t)BLTOT*CDIM];
DEVBUF float         g_v     [(size_t)BLTOT*CDIM];
DEVBUF __nv_bfloat16 g_vt_hi [(size_t)BLTOT*CDIM];   // [B][C][L]
DEVBUF __nv_bfloat16 g_vt_lo [(size_t)BLTOT*CDIM];
DEVBUF __nv_bfloat16 g_ctx_hi[(size_t)BLTOT*CDIM];
DEVBUF __nv_bfloat16 g_ctx_lo[(size_t)BLTOT*CDIM];
DEVBUF float         g_s     [(size_t)BATCH*LSEQ*LSEQ];   // 268 MB scores
DEVBUF __nv_bfloat16 g_p_hi  [(size_t)BATCH*LSEQ*LSEQ];
DEVBUF __nv_bfloat16 g_p_lo  [(size_t)BATCH*LSEQ*LSEQ];
DEVBUF __nv_bfloat16 g_wqT_hi[CDIM*CDIM]; DEVBUF __nv_bfloat16 g_wqT_lo[CDIM*CDIM];
DEVBUF __nv_bfloat16 g_wkT_hi[CDIM*CDIM]; DEVBUF __nv_bfloat16 g_wkT_lo[CDIM*CDIM];
DEVBUF __nv_bfloat16 g_wvT_hi[CDIM*CDIM]; DEVBUF __nv_bfloat16 g_wvT_lo[CDIM*CDIM];
DEVBUF __nv_bfloat16 g_woT_hi[CDIM*CDIM]; DEVBUF __nv_bfloat16 g_woT_lo[CDIM*CDIM];
static __device__ float g_mean[BATCH*GROUPS];
static __device__ float g_rstd[BATCH*GROUPS];

// ---------------------------------------------------------------------------
// PTX helpers (base sm_80+ features only — no tcgen05 on this target)
// ---------------------------------------------------------------------------
__device__ __forceinline__ uint32_t smem_u32(const void* p) {
    uint32_t a;
    asm("{ .reg .u64 t; cvta.to.shared.u64 t, %1; cvt.u32.u64 %0, t; }" : "=r"(a) : "l"(p));
    return a;
}
__device__ __forceinline__ void cp16(uint32_t dst, const void* src) {
    asm volatile("cp.async.cg.shared.global [%0], [%1], 16;" :: "r"(dst), "l"(src));
}
#define CP_COMMIT() asm volatile("cp.async.commit_group;" ::: "memory")
#define CP_WAIT1()  asm volatile("cp.async.wait_group 1;" ::: "memory")

__device__ __forceinline__ void ldsm4(uint32_t* r, uint32_t addr) {
    asm volatile("ldmatrix.sync.aligned.m8n8.x4.shared.b16 {%0,%1,%2,%3}, [%4];"
        : "=r"(r[0]), "=r"(r[1]), "=r"(r[2]), "=r"(r[3]) : "r"(addr));
}
__device__ __forceinline__ void mma16816(float* c, const uint32_t* a, const uint32_t* b) {
    asm volatile("mma.sync.aligned.m16n8k16.row.col.f32.bf16.bf16.f32 "
        "{%0,%1,%2,%3}, {%4,%5,%6,%7}, {%8,%9}, {%0,%1,%2,%3};"
        : "+f"(c[0]), "+f"(c[1]), "+f"(c[2]), "+f"(c[3])
        : "r"(a[0]), "r"(a[1]), "r"(a[2]), "r"(a[3]), "r"(b[0]), "r"(b[1]));
}
__device__ __forceinline__ void split2(float x, __nv_bfloat16& h, __nv_bfloat16& l) {
    h = __float2bfloat16(x);
    l = __float2bfloat16(x - __bfloat162float(h));
}

// ---------------------------------------------------------------------------
// GroupNorm stats
// ---------------------------------------------------------------------------
__global__ void __launch_bounds__(256) gn_stats_kernel(const float* __restrict__ x) {
    int b = blockIdx.x / GROUPS, g = blockIdx.x % GROUPS;
    const float* base = x + (size_t)b * LSEQ * CDIM + g * 16;
    float s = 0.f, s2 = 0.f;
    for (int l = threadIdx.x; l < LSEQ; l += 256) {
        const float4* p = (const float4*)(base + (size_t)l * CDIM);
        #pragma unroll
        for (int j = 0; j < 4; ++j) {
            float4 v = p[j];
            s  += v.x + v.y + v.z + v.w;
            s2 += v.x*v.x + v.y*v.y + v.z*v.z + v.w*v.w;
        }
    }
    __shared__ float sh1[256], sh2[256];
    sh1[threadIdx.x] = s; sh2[threadIdx.x] = s2;
    __syncthreads();
    for (int st = 128; st > 0; st >>= 1) {
        if (threadIdx.x < st) { sh1[threadIdx.x] += sh1[threadIdx.x+st]; sh2[threadIdx.x] += sh2[threadIdx.x+st]; }
        __syncthreads();
    }
    if (threadIdx.x == 0) {
        const float inv = 1.f / (float)(LSEQ * 16);
        float m = sh1[0] * inv;
        g_mean[blockIdx.x] = m;
        g_rstd[blockIdx.x] = rsqrtf(sh2[0]*inv - m*m + EPS_GN);
    }
}

// ---------------------------------------------------------------------------
// Normalize + affine -> split bf16 xn
// ---------------------------------------------------------------------------
__global__ void __launch_bounds__(256) gn_norm_split(const float* __restrict__ x,
                                                     const float* __restrict__ w,
                                                     const float* __restrict__ bb) {
    size_t i = ((size_t)blockIdx.x * 256 + threadIdx.x) * 4;
    int c = (int)(i & (CDIM - 1));
    int b = (int)(i >> 21);
    int gidx = b * GROUPS + (c >> 4);
    float m = g_mean[gidx], r = g_rstd[gidx];
    float4 v  = *(const float4*)(x + i);
    float4 gw = *(const float4*)(w + c);
    float4 gb = *(const float4*)(bb + c);
    float o0 = (v.x-m)*r*gw.x + gb.x, o1 = (v.y-m)*r*gw.y + gb.y;
    float o2 = (v.z-m)*r*gw.z + gb.z, o3 = (v.w-m)*r*gw.w + gb.w;
    __nv_bfloat16 h0,h1,h2,h3,l0,l1,l2,l3;
    split2(o0,h0,l0); split2(o1,h1,l1); split2(o2,h2,l2); split2(o3,h3,l3);
    uint2 hv, lv;
    hv.x = (uint32_t)__bfloat16_as_ushort(h0) | ((uint32_t)__bfloat16_as_ushort(h1) << 16);
    hv.y = (uint32_t)__bfloat16_as_ushort(h2) | ((uint32_t)__bfloat16_as_ushort(h3) << 16);
    lv.x = (uint32_t)__bfloat16_as_ushort(l0) | ((uint32_t)__bfloat16_as_ushort(l1) << 16);
    lv.y = (uint32_t)__bfloat16_as_ushort(l2) | ((uint32_t)__bfloat16_as_ushort(l3) << 16);
    *(uint2*)(g_xn_hi + i) = hv;
    *(uint2*)(g_xn_lo + i) = lv;
}

// ---------------------------------------------------------------------------
// Transpose + split: out[z][c][r] = in[z][r][c]  (fp32 -> bf16 hi/lo)
// ---------------------------------------------------------------------------
__global__ void transpose_split(const float* __restrict__ in,
                                __nv_bfloat16* __restrict__ oh,
                                __nv_bfloat16* __restrict__ ol,
                                int rows, int cols, size_t strideIn, size_t strideOut) {
    __shared__ float t[32][33];
    int c0 = blockIdx.x * 32, r0 = blockIdx.y * 32, z = blockIdx.z;
    const float* I = in + (size_t)z * strideIn;
    for (int dy = threadIdx.y; dy < 32; dy += 8)
        t[dy][threadIdx.x] = I[(size_t)(r0 + dy) * cols + c0 + threadIdx.x];
    __syncthreads();
    for (int dy = threadIdx.y; dy < 32; dy += 8) {
        float v = t[threadIdx.x][dy];
        __nv_bfloat16 h, l; split2(v, h, l);
        size_t o = (size_t)z * strideOut + (size_t)(c0 + dy) * rows + r0 + threadIdx.x;
        oh[o] = h; ol[o] = l;
    }
}

// ---------------------------------------------------------------------------
// Row softmax over g_s -> split bf16 P
// ---------------------------------------------------------------------------
__global__ void __launch_bounds__(256) softmax_split() {
    const float* row = g_s + (size_t)blockIdx.x * LSEQ;
    __nv_bfloat16* ph = g_p_hi + (size_t)blockIdx.x * LSEQ;
    __nv_bfloat16* pl = g_p_lo + (size_t)blockIdx.x * LSEQ;
    int t = threadIdx.x;
    float v[16];
    float m = -1e30f;
    #pragma unroll
    for (int j = 0; j < 16; ++j) { v[j] = row[t + j*256]; m = fmaxf(m, v[j]); }
    __shared__ float sh[256];
    sh[t] = m; __syncthreads();
    for (int st = 128; st > 0; st >>= 1) { if (t < st) sh[t] = fmaxf(sh[t], sh[t+st]); __syncthreads(); }
    m = sh[0]; __syncthreads();
    float s = 0.f;
    #pragma unroll
    for (int j = 0; j < 16; ++j) { v[j] = __expf(v[j] - m); s += v[j]; }
    sh[t] = s; __syncthreads();
    for (int st = 128; st > 0; st >>= 1) { if (t < st) sh[t] += sh[t+st]; __syncthreads(); }
    float inv = 1.f / sh[0];
    #pragma unroll
    for (int j = 0; j < 16; ++j) {
        __nv_bfloat16 h, l; split2(v[j] * inv, h, l);
        ph[t + j*256] = h; pl[t + j*256] = l;
    }
}

// ---------------------------------------------------------------------------
// Split-bf16 GEMM via mma.sync: D[M,N] = alpha*(A @ B^T) (+bias) (+resid)
//   A [M,K] hi/lo bf16 K-major; B [N,K] hi/lo bf16 K-major.
//   OUTMODE 0: fp32 out. OUTMODE 1: split bf16 out.
// ---------------------------------------------------------------------------
__device__ __forceinline__ void load_stage(
    uint32_t sbase,
    const __nv_bfloat16* __restrict__ Ahi, const __nv_bfloat16* __restrict__ Alo,
    const __nv_bfloat16* __restrict__ Bhi, const __nv_bfloat16* __restrict__ Blo,
    int row0, int col0, int kk, int ldA, int ldB, int tid)
{
    #pragma unroll
    for (int j = 0; j < 2; ++j) {
        int idx = tid + 256*j;                 // 0..511
        int r = idx >> 2, k16 = idx & 3;
        uint32_t so = sbase + (uint32_t)(r*ROWB + k16*16);
        size_t go = (size_t)(row0 + r) * ldA + kk + k16*8;
        cp16(so,          Ahi + go);
        cp16(so + TILE_B, Alo + go);
    }
    #pragma unroll
    for (int j = 0; j < 2; ++j) {
        int idx = tid + 256*j;
        int r = idx >> 2, k16 = idx & 3;
        uint32_t so = sbase + 2*TILE_B + (uint32_t)(r*ROWB + k16*16);
        size_t go = (size_t)(col0 + r) * ldB + kk + k16*8;
        cp16(so,          Bhi + go);
        cp16(so + TILE_B, Blo + go);
    }
}

template<int OUTMODE>
__global__ void __launch_bounds__(256, 1) mma_gemm(
    const __nv_bfloat16* __restrict__ Ahi, const __nv_bfloat16* __restrict__ Alo,
    const __nv_bfloat16* __restrict__ Bhi, const __nv_bfloat16* __restrict__ Blo,
    float* __restrict__ Cf, __nv_bfloat16* __restrict__ Chi, __nv_bfloat16* __restrict__ Clo,
    int K, int ldA, int ldB, int ldC,
    size_t sA, size_t sB, size_t sC,
    float alpha, const float* __restrict__ bias, const float* __restrict__ resid)
{
    extern __shared__ __align__(128) char smem[];
    const uint32_t sb0 = smem_u32(smem);
    const int tid = threadIdx.x;
    const int lane = tid & 31, wid = tid >> 5;
    const int wm = wid & 1, wn = wid >> 1;        // warps 2 x 4
    const int row0 = blockIdx.y * BM;
    const int col0 = blockIdx.x * BN;
    Ahi += sA * blockIdx.z; Alo += sA * blockIdx.z;
    Bhi += sB * blockIdx.z; Blo += sB * blockIdx.z;
    const size_t zC = sC * blockIdx.z;

    const int g = lane >> 3, r = lane & 7;
    const uint32_t aoff = (uint32_t)((wm*64 + (g&1)*8 + r) * ROWB + (g>>1)*16);
    const uint32_t boff = (uint32_t)((wn*32 + (g>>1)*8 + r) * ROWB + (g&1)*16);

    float acc[4][4][4];
    #pragma unroll
    for (int a1 = 0; a1 < 4; ++a1)
        #pragma unroll
        for (int a2 = 0; a2 < 4; ++a2)
            #pragma unroll
            for (int a3 = 0; a3 < 4; ++a3) acc[a1][a2][a3] = 0.f;

    const int nch = K / BK;
    load_stage(sb0,           Ahi, Alo, Bhi, Blo, row0, col0, 0,  ldA, ldB, tid); CP_COMMIT();
    load_stage(sb0 + STAGE_B, Ahi, Alo, Bhi, Blo, row0, col0, BK, ldA, ldB, tid); CP_COMMIT();

    for (int i = 0; i < nch; ++i) {
        CP_WAIT1();
        __syncthreads();
        const int nxt = i + 2;
        if (nxt < nch)
            load_stage(sb0 + (uint32_t)((nxt % NSTAGE) * STAGE_B),
                       Ahi, Alo, Bhi, Blo, row0, col0, nxt * BK, ldA, ldB, tid);
        CP_COMMIT();

        const uint32_t sb = sb0 + (uint32_t)((i % NSTAGE) * STAGE_B);
        #pragma unroll
        for (int ks = 0; ks < 2; ++ks) {
            uint32_t ah[4][4], al[4][4], bh[2][4], bl[2][4];
            #pragma unroll
            for (int mf = 0; mf < 4; ++mf) {
                uint32_t ad = sb + aoff + (uint32_t)(mf*(16*ROWB) + ks*32);
                ldsm4(ah[mf], ad);
                ldsm4(al[mf], ad + TILE_B);
            }
            #pragma unroll
            for (int nf = 0; nf < 2; ++nf) {
                uint32_t bd = sb + 2*TILE_B + boff + (uint32_t)(nf*(16*ROWB) + ks*32);
                ldsm4(bh[nf], bd);
                ldsm4(bl[nf], bd + TILE_B);
            }
            #pragma unroll
            for (int mf = 0; mf < 4; ++mf)
                #pragma unroll
                for (int nf = 0; nf < 2; ++nf)
                    #pragma unroll
                    for (int n8 = 0; n8 < 2; ++n8) {
                        float* c = acc[mf][nf*2 + n8];
                        const uint32_t* bhp = &bh[nf][n8*2];
                        const uint32_t* blp = &bl[nf][n8*2];
                        mma16816(c, ah[mf], bhp);
                        mma16816(c, ah[mf], blp);
                        mma16816(c, al[mf], bhp);
                    }
        }
    }

    // Epilogue: accumulators straight to GMEM
    #pragma unroll
    for (int mf = 0; mf < 4; ++mf) {
        #pragma unroll
        for (int nf = 0; nf < 2; ++nf) {
            #pragma unroll
            for (int n8 = 0; n8 < 2; ++n8) {
                float* c = acc[mf][nf*2 + n8];
                const int col = col0 + wn*32 + nf*16 + n8*8 + 2*(lane & 3);
                const int rlo = row0 + wm*64 + mf*16 + (lane >> 2);
                float v0 = c[0]*alpha, v1 = c[1]*alpha, v2 = c[2]*alpha, v3 = c[3]*alpha;
                if (bias) {
                    float b0 = bias[col], b1 = bias[col+1];
                    v0 += b0; v1 += b1; v2 += b0; v3 += b1;
                }
                const size_t o0 = zC + (size_t)rlo * ldC + col;
                const size_t o1 = zC + (size_t)(rlo + 8) * ldC + col;
                if (OUTMODE == 0) {
                    if (resid) {
                        float2 r0v = *(const float2*)(resid + o0);
                        float2 r1v = *(const float2*)(resid + o1);
                        v0 += r0v.x; v1 += r0v.y; v2 += r1v.x; v3 += r1v.y;
                    }
                    *(float2*)(Cf + o0) = make_float2(v0, v1);
                    *(float2*)(Cf + o1) = make_float2(v2, v3);
                } else {
                    __nv_bfloat16 h0,h1,h2,h3,l0,l1,l2,l3;
                    split2(v0,h0,l0); split2(v1,h1,l1); split2(v2,h2,l2); split2(v3,h3,l3);
                    uint32_t hv0 = (uint32_t)__bfloat16_as_ushort(h0) | ((uint32_t)__bfloat16_as_ushort(h1) << 16);
                    uint32_t hv1 = (uint32_t)__bfloat16_as_ushort(h2) | ((uint32_t)__bfloat16_as_ushort(h3) << 16);
                    uint32_t lv0 = (uint32_t)__bfloat16_as_ushort(l0) | ((uint32_t)__bfloat16_as_ushort(l1) << 16);
                    uint32_t lv1 = (uint32_t)__bfloat16_as_ushort(l2) | ((uint32_t)__bfloat16_as_ushort(l3) << 16);
                    *(uint32_t*)(Chi + o0) = hv0;
                    *(uint32_t*)(Chi + o1) = hv1;
                    *(uint32_t*)(Clo + o0) = lv0;
                    *(uint32_t*)(Clo + o1) = lv1;
                }
            }
        }
    }
}

// ---------------------------------------------------------------------------
// Launch
// ---------------------------------------------------------------------------
#define SYM(p, s) do { void* _t = nullptr; cudaGetSymbolAddress(&_t, s); p = (decltype(p))_t; } while (0)

extern "C" void kernel_launch(void* const* d_in, const int* in_sizes, int n_in,
                              void* d_out, int out_size) {
    const float* x   = (const float*)d_in[0];
    const float* gnw = (const float*)d_in[1];
    const float* gnb = (const float*)d_in[2];
    const float* wq  = (const float*)d_in[3];
    const float* bq  = (const float*)d_in[4];
    const float* wk  = (const float*)d_in[5];
    const float* bk  = (const float*)d_in[6];
    const float* wv  = (const float*)d_in[7];
    const float* bv  = (const float*)d_in[8];
    const float* wo  = (const float*)d_in[9];
    const float* bo  = (const float*)d_in[10];
    float* out = (float*)d_out;

    static int smem_set = 0;
    cudaFuncSetAttribute(mma_gemm<0>, cudaFuncAttributeMaxDynamicSharedMemorySize, SMEM_TOTAL);
    cudaFuncSetAttribute(mma_gemm<1>, cudaFuncAttributeMaxDynamicSharedMemorySize, SMEM_TOTAL);
    (void)smem_set;

    __nv_bfloat16 *xnh,*xnl,*qh,*ql,*kh,*kl,*vth,*vtl,*cxh,*cxl,*pph,*ppl;
    __nv_bfloat16 *wqh,*wql,*wkh,*wkl,*wvh,*wvl,*woh,*wol;
    float *vf, *sf;
    SYM(xnh, g_xn_hi);  SYM(xnl, g_xn_lo);
    SYM(qh,  g_q_hi);   SYM(ql,  g_q_lo);
    SYM(kh,  g_k_hi);   SYM(kl,  g_k_lo);
    SYM(vf,  g_v);      SYM(sf,  g_s);
    SYM(vth, g_vt_hi);  SYM(vtl, g_vt_lo);
    SYM(cxh, g_ctx_hi); SYM(cxl, g_ctx_lo);
    SYM(pph, g_p_hi);   SYM(ppl, g_p_lo);
    SYM(wqh, g_wqT_hi); SYM(wql, g_wqT_lo);
    SYM(wkh, g_wkT_hi); SYM(wkl, g_wkT_lo);
    SYM(wvh, g_wvT_hi); SYM(wvl, g_wvT_lo);
    SYM(woh, g_woT_hi); SYM(wol, g_woT_lo);

    const size_t LC = (size_t)LSEQ * CDIM;
    const size_t LL = (size_t)LSEQ * LSEQ;
    const float attn_scale = 1.f / sqrtf((float)CDIM);

    // 1) GroupNorm -> split xn
    gn_stats_kernel<<<BATCH * GROUPS, 256>>>(x);
    gn_norm_split<<<8192, 256>>>(x, gnw, gnb);

    // 2) transpose+split weights: wT[n][k] = w[k][n]
    dim3 tw(32, 8);
    dim3 gw(CDIM/32, CDIM/32, 1);
    transpose_split<<<gw, tw>>>(wq, wqh, wql, CDIM, CDIM, 0, 0);
    transpose_split<<<gw, tw>>>(wk, wkh, wkl, CDIM, CDIM, 0, 0);
    transpose_split<<<gw, tw>>>(wv, wvh, wvl, CDIM, CDIM, 0, 0);
    transpose_split<<<gw, tw>>>(wo, woh, wol, CDIM, CDIM, 0, 0);

    // 3) QKV projections: [16384,512] x [512,512]^T
    dim3 grid_qkv(CDIM/BN, BLTOT/BM, 1);
    mma_gemm<1><<<grid_qkv, 256, SMEM_TOTAL>>>(xnh, xnl, wqh, wql,
        nullptr, qh, ql, CDIM, CDIM, CDIM, CDIM, 0, 0, 0, 1.f, bq, nullptr);
    mma_gemm<1><<<grid_qkv, 256, SMEM_TOTAL>>>(xnh, xnl, wkh, wkl,
        nullptr, kh, kl, CDIM, CDIM, CDIM, CDIM, 0, 0, 0, 1.f, bk, nullptr);
    mma_gemm<0><<<grid_qkv, 256, SMEM_TOTAL>>>(xnh, xnl, wvh, wvl,
        vf, nullptr, nullptr, CDIM, CDIM, CDIM, CDIM, 0, 0, 0, 1.f, bv, nullptr);

    // 4) V^T split: vt[b][c][l] = v[b][l][c]
    transpose_split<<<dim3(CDIM/32, LSEQ/32, BATCH), tw>>>(vf, vth, vtl, LSEQ, CDIM, LC, LC);

    // 5) scores = scale * Q @ K^T   (per batch)
    dim3 grid_s(LSEQ/BN, LSEQ/BM, BATCH);
    mma_gemm<0><<<grid_s, 256, SMEM_TOTAL>>>(qh, ql, kh, kl,
        sf, nullptr, nullptr, CDIM, CDIM, CDIM, LSEQ, LC, LC, LL,
        attn_scale, nullptr, nullptr);

    // 6) softmax -> split P
    softmax_split<<<BATCH * LSEQ, 256>>>();

    // 7) ctx = P @ V  (B operand = V^T, K = L)
    dim3 grid_pv(CDIM/BN, LSEQ/BM, BATCH);
    mma_gemm<1><<<grid_pv, 256, SMEM_TOTAL>>>(pph, ppl, vth, vtl,
        nullptr, cxh, cxl, LSEQ, LSEQ, LSEQ, CDIM, LL, LC, LC,
        1.f, nullptr, nullptr);

    // 8) out = ctx @ wo^T + bo + residual
    mma_gemm<0><<<grid_qkv, 256, SMEM_TOTAL>>>(cxh, cxl, woh, wol,
        out, nullptr, nullptr, CDIM, CDIM, CDIM, CDIM, 0, 0, 0,
        1.f, bo, x);
}

// round 6
// speedup vs baseline: 5.6207x; 2.4117x over previous
#include <cuda_runtime.h>
#include <cuda_bf16.h>
#include <math.h>
#include <stdint.h>

#define BATCH  4
#define LSEQ   4096
#define CDIM   512
#define BLTOT  (BATCH*LSEQ)
#define GROUPS 32
#define EPS_GN 1e-6f

// ---- mma.sync GEMM tiling ----
#define BM 128
#define BN 256
#define BK 32
#define ROWB    80                    // SMEM row stride bytes (32 bf16 + 8 skew)
#define A_TILE_B (BM*ROWB)            // 10240 B
#define B_TILE_B (BN*ROWB)            // 20480 B
#define STAGE_B  (A_TILE_B + B_TILE_B) // 30720 B
#define NSTAGE 4
#define SMEM_TOTAL (NSTAGE*STAGE_B)   // 122880 B

// ---------------------------------------------------------------------------
// Scratch (static device globals)
// ---------------------------------------------------------------------------
#define DEVBUF static __device__ __align__(16)
DEVBUF __nv_bfloat16 g_xn [(size_t)BLTOT*CDIM];
DEVBUF __nv_bfloat16 g_q  [(size_t)BLTOT*CDIM];
DEVBUF __nv_bfloat16 g_k  [(size_t)BLTOT*CDIM];
DEVBUF float         g_v  [(size_t)BLTOT*CDIM];
DEVBUF __nv_bfloat16 g_vt [(size_t)BLTOT*CDIM];     // [B][C][L]
DEVBUF __nv_bfloat16 g_ctx[(size_t)BLTOT*CDIM];
DEVBUF float         g_s  [(size_t)BATCH*LSEQ*LSEQ]; // 268 MB scores fp32
DEVBUF __nv_bfloat16 g_p  [(size_t)BATCH*LSEQ*LSEQ]; // 134 MB probs bf16
DEVBUF __nv_bfloat16 g_wqT[CDIM*CDIM];
DEVBUF __nv_bfloat16 g_wkT[CDIM*CDIM];
DEVBUF __nv_bfloat16 g_wvT[CDIM*CDIM];
DEVBUF __nv_bfloat16 g_woT[CDIM*CDIM];
static __device__ float g_mean[BATCH*GROUPS];
static __device__ float g_rstd[BATCH*GROUPS];

// ---------------------------------------------------------------------------
// PTX helpers (base sm_80+ features only)
// ---------------------------------------------------------------------------
__device__ __forceinline__ uint32_t smem_u32(const void* p) {
    uint32_t a;
    asm("{ .reg .u64 t; cvta.to.shared.u64 t, %1; cvt.u32.u64 %0, t; }" : "=r"(a) : "l"(p));
    return a;
}
__device__ __forceinline__ void cp16(uint32_t dst, const void* src) {
    asm volatile("cp.async.cg.shared.global [%0], [%1], 16;" :: "r"(dst), "l"(src));
}
#define CP_COMMIT() asm volatile("cp.async.commit_group;" ::: "memory")
#define CP_WAIT2()  asm volatile("cp.async.wait_group 2;" ::: "memory")

__device__ __forceinline__ void ldsm4(uint32_t* r, uint32_t addr) {
    asm volatile("ldmatrix.sync.aligned.m8n8.x4.shared.b16 {%0,%1,%2,%3}, [%4];"
        : "=r"(r[0]), "=r"(r[1]), "=r"(r[2]), "=r"(r[3]) : "r"(addr));
}
__device__ __forceinline__ void mma16816(float* c, const uint32_t* a, const uint32_t* b) {
    asm volatile("mma.sync.aligned.m16n8k16.row.col.f32.bf16.bf16.f32 "
        "{%0,%1,%2,%3}, {%4,%5,%6,%7}, {%8,%9}, {%0,%1,%2,%3};"
        : "+f"(c[0]), "+f"(c[1]), "+f"(c[2]), "+f"(c[3])
        : "r"(a[0]), "r"(a[1]), "r"(a[2]), "r"(a[3]), "r"(b[0]), "r"(b[1]));
}

// ---------------------------------------------------------------------------
// GroupNorm stats
// ---------------------------------------------------------------------------
__global__ void __launch_bounds__(256) gn_stats_kernel(const float* __restrict__ x) {
    int b = blockIdx.x / GROUPS, g = blockIdx.x % GROUPS;
    const float* base = x + (size_t)b * LSEQ * CDIM + g * 16;
    float s = 0.f, s2 = 0.f;
    for (int l = threadIdx.x; l < LSEQ; l += 256) {
        const float4* p = (const float4*)(base + (size_t)l * CDIM);
        #pragma unroll
        for (int j = 0; j < 4; ++j) {
            float4 v = p[j];
            s  += v.x + v.y + v.z + v.w;
            s2 += v.x*v.x + v.y*v.y + v.z*v.z + v.w*v.w;
        }
    }
    __shared__ float sh1[256], sh2[256];
    sh1[threadIdx.x] = s; sh2[threadIdx.x] = s2;
    __syncthreads();
    for (int st = 128; st > 0; st >>= 1) {
        if (threadIdx.x < st) { sh1[threadIdx.x] += sh1[threadIdx.x+st]; sh2[threadIdx.x] += sh2[threadIdx.x+st]; }
        __syncthreads();
    }
    if (threadIdx.x == 0) {
        const float inv = 1.f / (float)(LSEQ * 16);
        float m = sh1[0] * inv;
        g_mean[blockIdx.x] = m;
        g_rstd[blockIdx.x] = rsqrtf(sh2[0]*inv - m*m + EPS_GN);
    }
}

// ---------------------------------------------------------------------------
// Normalize + affine -> bf16 xn
// ---------------------------------------------------------------------------
__global__ void __launch_bounds__(256) gn_norm_bf16(const float* __restrict__ x,
                                                    const float* __restrict__ w,
                                                    const float* __restrict__ bb) {
    size_t i = ((size_t)blockIdx.x * 256 + threadIdx.x) * 4;
    int c = (int)(i & (CDIM - 1));
    int b = (int)(i >> 21);
    int gidx = b * GROUPS + (c >> 4);
    float m = g_mean[gidx], r = g_rstd[gidx];
    float4 v  = *(const float4*)(x + i);
    float4 gw = *(const float4*)(w + c);
    float4 gb = *(const float4*)(bb + c);
    float o0 = (v.x-m)*r*gw.x + gb.x, o1 = (v.y-m)*r*gw.y + gb.y;
    float o2 = (v.z-m)*r*gw.z + gb.z, o3 = (v.w-m)*r*gw.w + gb.w;
    uint2 hv;
    hv.x = (uint32_t)__bfloat16_as_ushort(__float2bfloat16(o0)) |
           ((uint32_t)__bfloat16_as_ushort(__float2bfloat16(o1)) << 16);
    hv.y = (uint32_t)__bfloat16_as_ushort(__float2bfloat16(o2)) |
           ((uint32_t)__bfloat16_as_ushort(__float2bfloat16(o3)) << 16);
    *(uint2*)(g_xn + i) = hv;
}

// ---------------------------------------------------------------------------
// Transpose fp32 -> bf16: out[z][c][r] = in[z][r][c]
// ---------------------------------------------------------------------------
__global__ void transpose_bf16(const float* __restrict__ in,
                               __nv_bfloat16* __restrict__ oh,
                               int rows, int cols, size_t strideIn, size_t strideOut) {
    __shared__ float t[32][33];
    int c0 = blockIdx.x * 32, r0 = blockIdx.y * 32, z = blockIdx.z;
    const float* I = in + (size_t)z * strideIn;
    for (int dy = threadIdx.y; dy < 32; dy += 8)
        t[dy][threadIdx.x] = I[(size_t)(r0 + dy) * cols + c0 + threadIdx.x];
    __syncthreads();
    for (int dy = threadIdx.y; dy < 32; dy += 8) {
        size_t o = (size_t)z * strideOut + (size_t)(c0 + dy) * rows + r0 + threadIdx.x;
        oh[o] = __float2bfloat16(t[threadIdx.x][dy]);
    }
}

// ---------------------------------------------------------------------------
// Row softmax over fp32 scores -> bf16 P
// ---------------------------------------------------------------------------
__global__ void __launch_bounds__(256) softmax_bf16() {
    const float* row = g_s + (size_t)blockIdx.x * LSEQ;
    __nv_bfloat16* ph = g_p + (size_t)blockIdx.x * LSEQ;
    int t = threadIdx.x;
    float v[16];
    float m = -1e30f;
    #pragma unroll
    for (int j = 0; j < 16; ++j) { v[j] = row[t + j*256]; m = fmaxf(m, v[j]); }
    __shared__ float sh[256];
    sh[t] = m; __syncthreads();
    for (int st = 128; st > 0; st >>= 1) { if (t < st) sh[t] = fmaxf(sh[t], sh[t+st]); __syncthreads(); }
    m = sh[0]; __syncthreads();
    float s = 0.f;
    #pragma unroll
    for (int j = 0; j < 16; ++j) { v[j] = __expf(v[j] - m); s += v[j]; }
    sh[t] = s; __syncthreads();
    for (int st = 128; st > 0; st >>= 1) { if (t < st) sh[t] += sh[t+st]; __syncthreads(); }
    float inv = 1.f / sh[0];
    #pragma unroll
    for (int j = 0; j < 16; ++j)
        ph[t + j*256] = __float2bfloat16(v[j] * inv);
}

// ---------------------------------------------------------------------------
// bf16 GEMM via mma.sync: D[M,N] = alpha*(A @ B^T) (+bias) (+resid)
//   A [M,K] bf16 K-major; B [N,K] bf16 K-major.
//   OUTMODE 0: fp32 out (+resid). OUTMODE 1: bf16 out.
//   512 threads: warps 4(m) x 4(n); warp tile 32x64; 4-stage cp.async.
// ---------------------------------------------------------------------------
__device__ __forceinline__ void load_stage(
    uint32_t sbase,
    const __nv_bfloat16* __restrict__ A, const __nv_bfloat16* __restrict__ B,
    int row0, int col0, int kk, int ldA, int ldB, int tid)
{
    {   // A: 128 rows x 32 cols = 512 cp16, one per thread
        int r = tid >> 2, k16 = tid & 3;
        cp16(sbase + (uint32_t)(r*ROWB + k16*16),
             A + (size_t)(row0 + r) * ldA + kk + k16*8);
    }
    #pragma unroll
    for (int j = 0; j < 2; ++j) {   // B: 256 rows x 32 cols = 1024 cp16
        int idx = tid + 512*j;
        int r = idx >> 2, k16 = idx & 3;
        cp16(sbase + A_TILE_B + (uint32_t)(r*ROWB + k16*16),
             B + (size_t)(col0 + r) * ldB + kk + k16*8);
    }
}

template<int OUTMODE>
__global__ void __launch_bounds__(512, 1) mma_gemm(
    const __nv_bfloat16* __restrict__ A, const __nv_bfloat16* __restrict__ B,
    float* __restrict__ Cf, __nv_bfloat16* __restrict__ Cb,
    int K, int ldA, int ldB, int ldC,
    size_t sA, size_t sB, size_t sC,
    float alpha, const float* __restrict__ bias, const float* __restrict__ resid)
{
    extern __shared__ __align__(128) char smem[];
    const uint32_t sb0 = smem_u32(smem);
    const int tid = threadIdx.x;
    const int lane = tid & 31, wid = tid >> 5;
    const int wm = wid & 3, wn = wid >> 2;        // warps 4(m) x 4(n)
    const int row0 = blockIdx.y * BM;
    const int col0 = blockIdx.x * BN;
    A += sA * blockIdx.z; B += sB * blockIdx.z;
    const size_t zC = sC * blockIdx.z;

    const int g = lane >> 3, r = lane & 7;
    const uint32_t aoff = (uint32_t)((wm*32 + (g&1)*8 + r) * ROWB + (g>>1)*16);
    const uint32_t boff = (uint32_t)((wn*64 + (g>>1)*8 + r) * ROWB + (g&1)*16);

    float acc[2][8][4];
    #pragma unroll
    for (int a1 = 0; a1 < 2; ++a1)
        #pragma unroll
        for (int a2 = 0; a2 < 8; ++a2)
            #pragma unroll
            for (int a3 = 0; a3 < 4; ++a3) acc[a1][a2][a3] = 0.f;

    const int nch = K / BK;
    load_stage(sb0,             A, B, row0, col0, 0,    ldA, ldB, tid); CP_COMMIT();
    load_stage(sb0 + STAGE_B,   A, B, row0, col0, BK,   ldA, ldB, tid); CP_COMMIT();
    load_stage(sb0 + 2*STAGE_B, A, B, row0, col0, 2*BK, ldA, ldB, tid); CP_COMMIT();

    for (int i = 0; i < nch; ++i) {
        CP_WAIT2();
        __syncthreads();
        const int nxt = i + 3;
        if (nxt < nch)
            load_stage(sb0 + (uint32_t)((nxt & 3) * STAGE_B),
                       A, B, row0, col0, nxt * BK, ldA, ldB, tid);
        CP_COMMIT();

        const uint32_t sb = sb0 + (uint32_t)((i & 3) * STAGE_B);
        #pragma unroll
        for (int ks = 0; ks < 2; ++ks) {
            uint32_t ah[2][4], bh[4][4];
            #pragma unroll
            for (int mf = 0; mf < 2; ++mf)
                ldsm4(ah[mf], sb + aoff + (uint32_t)(mf*(16*ROWB) + ks*32));
            #pragma unroll
            for (int nf = 0; nf < 4; ++nf)
                ldsm4(bh[nf], sb + A_TILE_B + boff + (uint32_t)(nf*(16*ROWB) + ks*32));
            #pragma unroll
            for (int mf = 0; mf < 2; ++mf)
                #pragma unroll
                for (int nf = 0; nf < 4; ++nf)
                    #pragma unroll
                    for (int n8 = 0; n8 < 2; ++n8)
                        mma16816(acc[mf][nf*2 + n8], ah[mf], &bh[nf][n8*2]);
        }
    }

    // Epilogue
    #pragma unroll
    for (int mf = 0; mf < 2; ++mf) {
        #pragma unroll
        for (int nf = 0; nf < 4; ++nf) {
            #pragma unroll
            for (int n8 = 0; n8 < 2; ++n8) {
                float* c = acc[mf][nf*2 + n8];
                const int col = col0 + wn*64 + nf*16 + n8*8 + 2*(lane & 3);
                const int rlo = row0 + wm*32 + mf*16 + (lane >> 2);
                float v0 = c[0]*alpha, v1 = c[1]*alpha, v2 = c[2]*alpha, v3 = c[3]*alpha;
                if (bias) {
                    float b0 = bias[col], b1 = bias[col+1];
                    v0 += b0; v1 += b1; v2 += b0; v3 += b1;
                }
                const size_t o0 = zC + (size_t)rlo * ldC + col;
                const size_t o1 = zC + (size_t)(rlo + 8) * ldC + col;
                if (OUTMODE == 0) {
                    if (resid) {
                        float2 r0v = *(const float2*)(resid + o0);
                        float2 r1v = *(const float2*)(resid + o1);
                        v0 += r0v.x; v1 += r0v.y; v2 += r1v.x; v3 += r1v.y;
                    }
                    *(float2*)(Cf + o0) = make_float2(v0, v1);
                    *(float2*)(Cf + o1) = make_float2(v2, v3);
                } else {
                    uint32_t hv0 = (uint32_t)__bfloat16_as_ushort(__float2bfloat16(v0)) |
                                   ((uint32_t)__bfloat16_as_ushort(__float2bfloat16(v1)) << 16);
                    uint32_t hv1 = (uint32_t)__bfloat16_as_ushort(__float2bfloat16(v2)) |
                                   ((uint32_t)__bfloat16_as_ushort(__float2bfloat16(v3)) << 16);
                    *(uint32_t*)(Cb + o0) = hv0;
                    *(uint32_t*)(Cb + o1) = hv1;
                }
            }
        }
    }
}

// ---------------------------------------------------------------------------
// Launch
// ---------------------------------------------------------------------------
#define SYM(p, s) do { void* _t = nullptr; cudaGetSymbolAddress(&_t, s); p = (decltype(p))_t; } while (0)

extern "C" void kernel_launch(void* const* d_in, const int* in_sizes, int n_in,
                              void* d_out, int out_size) {
    const float* x   = (const float*)d_in[0];
    const float* gnw = (const float*)d_in[1];
    const float* gnb = (const float*)d_in[2];
    const float* wq  = (const float*)d_in[3];
    const float* bq  = (const float*)d_in[4];
    const float* wk  = (const float*)d_in[5];
    const float* bk  = (const float*)d_in[6];
    const float* wv  = (const float*)d_in[7];
    const float* bv  = (const float*)d_in[8];
    const float* wo  = (const float*)d_in[9];
    const float* bo  = (const float*)d_in[10];
    float* out = (float*)d_out;

    cudaFuncSetAttribute(mma_gemm<0>, cudaFuncAttributeMaxDynamicSharedMemorySize, SMEM_TOTAL);
    cudaFuncSetAttribute(mma_gemm<1>, cudaFuncAttributeMaxDynamicSharedMemorySize, SMEM_TOTAL);

    __nv_bfloat16 *xn,*q,*k,*vt,*cx,*pp,*wqT,*wkT,*wvT,*woT;
    float *vf, *sf;
    SYM(xn,  g_xn);   SYM(q,   g_q);   SYM(k,   g_k);
    SYM(vf,  g_v);    SYM(sf,  g_s);
    SYM(vt,  g_vt);   SYM(cx,  g_ctx); SYM(pp,  g_p);
    SYM(wqT, g_wqT);  SYM(wkT, g_wkT); SYM(wvT, g_wvT); SYM(woT, g_woT);

    const size_t LC = (size_t)LSEQ * CDIM;
    const size_t LL = (size_t)LSEQ * LSEQ;
    const float attn_scale = 1.f / sqrtf((float)CDIM);

    // 1) GroupNorm -> bf16 xn
    gn_stats_kernel<<<BATCH * GROUPS, 256>>>(x);
    gn_norm_bf16<<<8192, 256>>>(x, gnw, gnb);

    // 2) transpose weights: wT[n][k] = w[k][n]
    dim3 tw(32, 8);
    dim3 gw(CDIM/32, CDIM/32, 1);
    transpose_bf16<<<gw, tw>>>(wq, wqT, CDIM, CDIM, 0, 0);
    transpose_bf16<<<gw, tw>>>(wk, wkT, CDIM, CDIM, 0, 0);
    transpose_bf16<<<gw, tw>>>(wv, wvT, CDIM, CDIM, 0, 0);
    transpose_bf16<<<gw, tw>>>(wo, woT, CDIM, CDIM, 0, 0);

    // 3) QKV projections: [16384,512] x [512,512]^T
    dim3 grid_qkv(CDIM/BN, BLTOT/BM, 1);
    mma_gemm<1><<<grid_qkv, 512, SMEM_TOTAL>>>(xn, wqT, nullptr, q,
        CDIM, CDIM, CDIM, CDIM, 0, 0, 0, 1.f, bq, nullptr);
    mma_gemm<1><<<grid_qkv, 512, SMEM_TOTAL>>>(xn, wkT, nullptr, k,
        CDIM, CDIM, CDIM, CDIM, 0, 0, 0, 1.f, bk, nullptr);
    mma_gemm<0><<<grid_qkv, 512, SMEM_TOTAL>>>(xn, wvT, vf, nullptr,
        CDIM, CDIM, CDIM, CDIM, 0, 0, 0, 1.f, bv, nullptr);

    // 4) V^T: vt[b][c][l] = v[b][l][c]
    transpose_bf16<<<dim3(CDIM/32, LSEQ/32, BATCH), tw>>>(vf, vt, LSEQ, CDIM, LC, LC);

    // 5) scores = scale * Q @ K^T  (fp32 out)
    dim3 grid_s(LSEQ/BN, LSEQ/BM, BATCH);
    mma_gemm<0><<<grid_s, 512, SMEM_TOTAL>>>(q, k, sf, nullptr,
        CDIM, CDIM, CDIM, LSEQ, LC, LC, LL, attn_scale, nullptr, nullptr);

    // 6) softmax -> bf16 P
    softmax_bf16<<<BATCH * LSEQ, 256>>>();

    // 7) ctx = P @ V  (B operand = V^T, K = L)
    dim3 grid_pv(CDIM/BN, LSEQ/BM, BATCH);
    mma_gemm<1><<<grid_pv, 512, SMEM_TOTAL>>>(pp, vt, nullptr, cx,
        LSEQ, LSEQ, LSEQ, CDIM, LL, LC, LC, 1.f, nullptr, nullptr);

    // 8) out = ctx @ wo^T + bo + residual
    mma_gemm<0><<<grid_qkv, 512, SMEM_TOTAL>>>(cx, woT, out, nullptr,
        CDIM, CDIM, CDIM, CDIM, 0, 0, 0, 1.f, bo, x);
}

// round 7
// speedup vs baseline: 6.1803x; 1.0996x over previous
#include <cuda_runtime.h>
#include <cuda_bf16.h>
#include <math.h>
#include <stdint.h>

#define BATCH  4
#define LSEQ   4096
#define CDIM   512
#define BLTOT  (BATCH*LSEQ)
#define GROUPS 32
#define EPS_GN 1e-6f
#define EXP_SHIFT 20.0f

// ---- mma.sync GEMM tiling ----
#define BM 128
#define BN 256
#define BK 32
#define ROWB    80                     // SMEM row stride bytes (32 bf16 + 8 skew)
#define A_TILE_B (BM*ROWB)             // 10240 B
#define B_TILE_B (BN*ROWB)             // 20480 B
#define STAGE_B  (A_TILE_B + B_TILE_B) // 30720 B
#define NSTAGE 4
#define SMEM_TOTAL (NSTAGE*STAGE_B)    // 122880 B

// ---------------------------------------------------------------------------
// Scratch (static device globals)
// ---------------------------------------------------------------------------
#define DEVBUF static __device__ __align__(16)
DEVBUF __nv_bfloat16 g_xn [(size_t)BLTOT*CDIM];
DEVBUF __nv_bfloat16 g_q  [(size_t)BLTOT*CDIM];
DEVBUF __nv_bfloat16 g_k  [(size_t)BLTOT*CDIM];
DEVBUF __nv_bfloat16 g_v  [(size_t)BLTOT*CDIM];
DEVBUF __nv_bfloat16 g_vt [(size_t)BLTOT*CDIM];      // [B][C][L]
DEVBUF __nv_bfloat16 g_ctx[(size_t)BLTOT*CDIM];
DEVBUF __nv_bfloat16 g_pun[(size_t)BATCH*LSEQ*LSEQ]; // 134 MB unnormalized probs
DEVBUF float         g_rowsum[BLTOT];
DEVBUF __nv_bfloat16 g_wqT[CDIM*CDIM];
DEVBUF __nv_bfloat16 g_wkT[CDIM*CDIM];
DEVBUF __nv_bfloat16 g_wvT[CDIM*CDIM];
DEVBUF __nv_bfloat16 g_woT[CDIM*CDIM];
static __device__ float g_mean[BATCH*GROUPS];
static __device__ float g_rstd[BATCH*GROUPS];

// ---------------------------------------------------------------------------
// PTX helpers (base sm_80+ features only)
// ---------------------------------------------------------------------------
__device__ __forceinline__ uint32_t smem_u32(const void* p) {
    uint32_t a;
    asm("{ .reg .u64 t; cvta.to.shared.u64 t, %1; cvt.u32.u64 %0, t; }" : "=r"(a) : "l"(p));
    return a;
}
__device__ __forceinline__ void cp16(uint32_t dst, const void* src) {
    asm volatile("cp.async.cg.shared.global [%0], [%1], 16;" :: "r"(dst), "l"(src));
}
#define CP_COMMIT()  asm volatile("cp.async.commit_group;" ::: "memory")
#define CP_WAIT2()   asm volatile("cp.async.wait_group 2;" ::: "memory")
#define CP_WAITALL() asm volatile("cp.async.wait_all;" ::: "memory")

__device__ __forceinline__ void ldsm4(uint32_t* r, uint32_t addr) {
    asm volatile("ldmatrix.sync.aligned.m8n8.x4.shared.b16 {%0,%1,%2,%3}, [%4];"
        : "=r"(r[0]), "=r"(r[1]), "=r"(r[2]), "=r"(r[3]) : "r"(addr));
}
__device__ __forceinline__ void mma16816(float* c, const uint32_t* a, const uint32_t* b) {
    asm volatile("mma.sync.aligned.m16n8k16.row.col.f32.bf16.bf16.f32 "
        "{%0,%1,%2,%3}, {%4,%5,%6,%7}, {%8,%9}, {%0,%1,%2,%3};"
        : "+f"(c[0]), "+f"(c[1]), "+f"(c[2]), "+f"(c[3])
        : "r"(a[0]), "r"(a[1]), "r"(a[2]), "r"(a[3]), "r"(b[0]), "r"(b[1]));
}
__device__ __forceinline__ uint32_t pack_bf16(float a, float b) {
    return (uint32_t)__bfloat16_as_ushort(__float2bfloat16(a)) |
           ((uint32_t)__bfloat16_as_ushort(__float2bfloat16(b)) << 16);
}

// ---------------------------------------------------------------------------
// GroupNorm stats
// ---------------------------------------------------------------------------
__global__ void __launch_bounds__(256) gn_stats_kernel(const float* __restrict__ x) {
    int b = blockIdx.x / GROUPS, g = blockIdx.x % GROUPS;
    const float* base = x + (size_t)b * LSEQ * CDIM + g * 16;
    float s = 0.f, s2 = 0.f;
    for (int l = threadIdx.x; l < LSEQ; l += 256) {
        const float4* p = (const float4*)(base + (size_t)l * CDIM);
        #pragma unroll
        for (int j = 0; j < 4; ++j) {
            float4 v = p[j];
            s  += v.x + v.y + v.z + v.w;
            s2 += v.x*v.x + v.y*v.y + v.z*v.z + v.w*v.w;
        }
    }
    __shared__ float sh1[256], sh2[256];
    sh1[threadIdx.x] = s; sh2[threadIdx.x] = s2;
    __syncthreads();
    for (int st = 128; st > 0; st >>= 1) {
        if (threadIdx.x < st) { sh1[threadIdx.x] += sh1[threadIdx.x+st]; sh2[threadIdx.x] += sh2[threadIdx.x+st]; }
        __syncthreads();
    }
    if (threadIdx.x == 0) {
        const float inv = 1.f / (float)(LSEQ * 16);
        float m = sh1[0] * inv;
        g_mean[blockIdx.x] = m;
        g_rstd[blockIdx.x] = rsqrtf(sh2[0]*inv - m*m + EPS_GN);
    }
}

// ---------------------------------------------------------------------------
// Normalize + affine -> bf16 xn
// ---------------------------------------------------------------------------
__global__ void __launch_bounds__(256) gn_norm_bf16(const float* __restrict__ x,
                                                    const float* __restrict__ w,
                                                    const float* __restrict__ bb) {
    size_t i = ((size_t)blockIdx.x * 256 + threadIdx.x) * 4;
    int c = (int)(i & (CDIM - 1));
    int b = (int)(i >> 21);
    int gidx = b * GROUPS + (c >> 4);
    float m = g_mean[gidx], r = g_rstd[gidx];
    float4 v  = *(const float4*)(x + i);
    float4 gw = *(const float4*)(w + c);
    float4 gb = *(const float4*)(bb + c);
    uint2 hv;
    hv.x = pack_bf16((v.x-m)*r*gw.x + gb.x, (v.y-m)*r*gw.y + gb.y);
    hv.y = pack_bf16((v.z-m)*r*gw.z + gb.z, (v.w-m)*r*gw.w + gb.w);
    *(uint2*)(g_xn + i) = hv;
}

// ---------------------------------------------------------------------------
// Transpose fp32 -> bf16 (weights)
// ---------------------------------------------------------------------------
__global__ void transpose_f2b(const float* __restrict__ in,
                              __nv_bfloat16* __restrict__ oh,
                              int rows, int cols) {
    __shared__ float t[32][33];
    int c0 = blockIdx.x * 32, r0 = blockIdx.y * 32;
    for (int dy = threadIdx.y; dy < 32; dy += 8)
        t[dy][threadIdx.x] = in[(size_t)(r0 + dy) * cols + c0 + threadIdx.x];
    __syncthreads();
    for (int dy = threadIdx.y; dy < 32; dy += 8)
        oh[(size_t)(c0 + dy) * rows + r0 + threadIdx.x] = __float2bfloat16(t[threadIdx.x][dy]);
}

// ---------------------------------------------------------------------------
// Transpose bf16 -> bf16 (V): out[z][c][r] = in[z][r][c]
// ---------------------------------------------------------------------------
__global__ void transpose_b2b(const __nv_bfloat16* __restrict__ in,
                              __nv_bfloat16* __restrict__ oh,
                              int rows, int cols, size_t strideIn, size_t strideOut) {
    __shared__ unsigned short t[32][33];
    int c0 = blockIdx.x * 32, r0 = blockIdx.y * 32, z = blockIdx.z;
    const __nv_bfloat16* I = in + (size_t)z * strideIn;
    for (int dy = threadIdx.y; dy < 32; dy += 8)
        t[dy][threadIdx.x] = __bfloat16_as_ushort(I[(size_t)(r0 + dy) * cols + c0 + threadIdx.x]);
    __syncthreads();
    for (int dy = threadIdx.y; dy < 32; dy += 8) {
        size_t o = (size_t)z * strideOut + (size_t)(c0 + dy) * rows + r0 + threadIdx.x;
        oh[o] = __ushort_as_bfloat16(t[threadIdx.x][dy]);
    }
}

// ---------------------------------------------------------------------------
// Zero rowsum
// ---------------------------------------------------------------------------
__global__ void zero_rowsum_kernel() {
    g_rowsum[blockIdx.x * 256 + threadIdx.x] = 0.f;
}

// ---------------------------------------------------------------------------
// bf16 GEMM via mma.sync: D[M,N] = A @ B^T variants.
//   OUTMODE 0: fp32 out, alpha, +bias, +resid         (output projection)
//   OUTMODE 1: bf16 out, +bias                        (Q/K/V projections)
//   OUTMODE 2: bf16 exp(alpha*s - SHIFT) out + rowsum (scores -> unnorm P)
//   OUTMODE 3: bf16 out scaled by 1/rowsum[row]       (P @ V)
// ---------------------------------------------------------------------------
__device__ __forceinline__ void load_stage(
    uint32_t sbase,
    const __nv_bfloat16* __restrict__ A, const __nv_bfloat16* __restrict__ B,
    int row0, int col0, int kk, int ldA, int ldB, int tid)
{
    {
        int r = tid >> 2, k16 = tid & 3;
        cp16(sbase + (uint32_t)(r*ROWB + k16*16),
             A + (size_t)(row0 + r) * ldA + kk + k16*8);
    }
    #pragma unroll
    for (int j = 0; j < 2; ++j) {
        int idx = tid + 512*j;
        int r = idx >> 2, k16 = idx & 3;
        cp16(sbase + A_TILE_B + (uint32_t)(r*ROWB + k16*16),
             B + (size_t)(col0 + r) * ldB + kk + k16*8);
    }
}

template<int OUTMODE>
__global__ void __launch_bounds__(512, 1) mma_gemm(
    const __nv_bfloat16* __restrict__ A, const __nv_bfloat16* __restrict__ B,
    float* __restrict__ Cf, __nv_bfloat16* __restrict__ Cb,
    float* __restrict__ rowsum,
    int K, int ldA, int ldB, int ldC,
    size_t sA, size_t sB, size_t sC,
    float alpha, const float* __restrict__ bias, const float* __restrict__ resid)
{
    extern __shared__ __align__(128) char smem[];
    const uint32_t sb0 = smem_u32(smem);
    const int tid = threadIdx.x;
    const int lane = tid & 31, wid = tid >> 5;
    const int wm = wid & 3, wn = wid >> 2;        // warps 4(m) x 4(n)
    const int row0 = blockIdx.y * BM;
    const int col0 = blockIdx.x * BN;
    A += sA * blockIdx.z; B += sB * blockIdx.z;
    const size_t zC = sC * blockIdx.z;
    float* rsumz = rowsum + (size_t)blockIdx.z * LSEQ;

    const int g = lane >> 3, r = lane & 7;
    const uint32_t aoff = (uint32_t)((wm*32 + (g&1)*8 + r) * ROWB + (g>>1)*16);
    const uint32_t boff = (uint32_t)((wn*64 + (g>>1)*8 + r) * ROWB + (g&1)*16);

    float acc[2][8][4];
    #pragma unroll
    for (int a1 = 0; a1 < 2; ++a1)
        #pragma unroll
        for (int a2 = 0; a2 < 8; ++a2)
            #pragma unroll
            for (int a3 = 0; a3 < 4; ++a3) acc[a1][a2][a3] = 0.f;

    const int nch = K / BK;
    load_stage(sb0,             A, B, row0, col0, 0,    ldA, ldB, tid); CP_COMMIT();
    load_stage(sb0 + STAGE_B,   A, B, row0, col0, BK,   ldA, ldB, tid); CP_COMMIT();
    load_stage(sb0 + 2*STAGE_B, A, B, row0, col0, 2*BK, ldA, ldB, tid); CP_COMMIT();

    for (int i = 0; i < nch; ++i) {
        CP_WAIT2();
        __syncthreads();
        const int nxt = i + 3;
        if (nxt < nch)
            load_stage(sb0 + (uint32_t)((nxt & 3) * STAGE_B),
                       A, B, row0, col0, nxt * BK, ldA, ldB, tid);
        CP_COMMIT();

        const uint32_t sb = sb0 + (uint32_t)((i & 3) * STAGE_B);
        #pragma unroll
        for (int ks = 0; ks < 2; ++ks) {
            uint32_t ah[2][4], bh[4][4];
            #pragma unroll
            for (int mf = 0; mf < 2; ++mf)
                ldsm4(ah[mf], sb + aoff + (uint32_t)(mf*(16*ROWB) + ks*32));
            #pragma unroll
            for (int nf = 0; nf < 4; ++nf)
                ldsm4(bh[nf], sb + A_TILE_B + boff + (uint32_t)(nf*(16*ROWB) + ks*32));
            #pragma unroll
            for (int mf = 0; mf < 2; ++mf)
                #pragma unroll
                for (int nf = 0; nf < 4; ++nf)
                    #pragma unroll
                    for (int n8 = 0; n8 < 2; ++n8)
                        mma16816(acc[mf][nf*2 + n8], ah[mf], &bh[nf][n8*2]);
        }
    }

    // ---- epilogue ----
    float rs[2][2];
    float* srow = (float*)smem;
    if (OUTMODE == 2) {
        rs[0][0] = rs[0][1] = rs[1][0] = rs[1][1] = 0.f;
        CP_WAITALL();
        __syncthreads();
        if (tid < BM) srow[tid] = 0.f;
        __syncthreads();
    }

    float inv0[2], inv1[2];
    if (OUTMODE == 3) {
        #pragma unroll
        for (int mf = 0; mf < 2; ++mf) {
            int rl = row0 + wm*32 + mf*16 + (lane >> 2);
            inv0[mf] = 1.f / rsumz[rl];
            inv1[mf] = 1.f / rsumz[rl + 8];
        }
    }

    #pragma unroll
    for (int mf = 0; mf < 2; ++mf) {
        #pragma unroll
        for (int nf = 0; nf < 4; ++nf) {
            #pragma unroll
            for (int n8 = 0; n8 < 2; ++n8) {
                float* c = acc[mf][nf*2 + n8];
                const int col = col0 + wn*64 + nf*16 + n8*8 + 2*(lane & 3);
                const int rlo = row0 + wm*32 + mf*16 + (lane >> 2);
                const size_t o0 = zC + (size_t)rlo * ldC + col;
                const size_t o1 = zC + (size_t)(rlo + 8) * ldC + col;
                if (OUTMODE == 2) {
                    float e0 = __expf(fmaf(c[0], alpha, -EXP_SHIFT));
                    float e1 = __expf(fmaf(c[1], alpha, -EXP_SHIFT));
                    float e2 = __expf(fmaf(c[2], alpha, -EXP_SHIFT));
                    float e3 = __expf(fmaf(c[3], alpha, -EXP_SHIFT));
                    rs[mf][0] += e0 + e1;
                    rs[mf][1] += e2 + e3;
                    *(uint32_t*)(Cb + o0) = pack_bf16(e0, e1);
                    *(uint32_t*)(Cb + o1) = pack_bf16(e2, e3);
                } else if (OUTMODE == 3) {
                    *(uint32_t*)(Cb + o0) = pack_bf16(c[0]*inv0[mf], c[1]*inv0[mf]);
                    *(uint32_t*)(Cb + o1) = pack_bf16(c[2]*inv1[mf], c[3]*inv1[mf]);
                } else {
                    float v0 = c[0]*alpha, v1 = c[1]*alpha, v2 = c[2]*alpha, v3 = c[3]*alpha;
                    if (bias) {
                        float b0 = bias[col], b1 = bias[col+1];
                        v0 += b0; v1 += b1; v2 += b0; v3 += b1;
                    }
                    if (OUTMODE == 0) {
                        if (resid) {
                            float2 r0v = *(const float2*)(resid + o0);
                            float2 r1v = *(const float2*)(resid + o1);
                            v0 += r0v.x; v1 += r0v.y; v2 += r1v.x; v3 += r1v.y;
                        }
                        *(float2*)(Cf + o0) = make_float2(v0, v1);
                        *(float2*)(Cf + o1) = make_float2(v2, v3);
                    } else {
                        *(uint32_t*)(Cb + o0) = pack_bf16(v0, v1);
                        *(uint32_t*)(Cb + o1) = pack_bf16(v2, v3);
                    }
                }
            }
        }
    }

    if (OUTMODE == 2) {
        #pragma unroll
        for (int mf = 0; mf < 2; ++mf)
            #pragma unroll
            for (int h = 0; h < 2; ++h) {
                rs[mf][h] += __shfl_xor_sync(0xffffffffu, rs[mf][h], 1);
                rs[mf][h] += __shfl_xor_sync(0xffffffffu, rs[mf][h], 2);
            }
        if ((lane & 3) == 0) {
            int lr = wm*32 + (lane >> 2);
            #pragma unroll
            for (int mf = 0; mf < 2; ++mf) {
                atomicAdd(&srow[lr + mf*16],     rs[mf][0]);
                atomicAdd(&srow[lr + mf*16 + 8], rs[mf][1]);
            }
        }
        __syncthreads();
        if (tid < BM) atomicAdd(&rsumz[row0 + tid], srow[tid]);
    }
}

// ---------------------------------------------------------------------------
// Launch
// ---------------------------------------------------------------------------
#define SYM(p, s) do { void* _t = nullptr; cudaGetSymbolAddress(&_t, s); p = (decltype(p))_t; } while (0)

extern "C" void kernel_launch(void* const* d_in, const int* in_sizes, int n_in,
                              void* d_out, int out_size) {
    const float* x   = (const float*)d_in[0];
    const float* gnw = (const float*)d_in[1];
    const float* gnb = (const float*)d_in[2];
    const float* wq  = (const float*)d_in[3];
    const float* bq  = (const float*)d_in[4];
    const float* wk  = (const float*)d_in[5];
    const float* bk  = (const float*)d_in[6];
    const float* wv  = (const float*)d_in[7];
    const float* bv  = (const float*)d_in[8];
    const float* wo  = (const float*)d_in[9];
    const float* bo  = (const float*)d_in[10];
    float* out = (float*)d_out;

    cudaFuncSetAttribute(mma_gemm<0>, cudaFuncAttributeMaxDynamicSharedMemorySize, SMEM_TOTAL);
    cudaFuncSetAttribute(mma_gemm<1>, cudaFuncAttributeMaxDynamicSharedMemorySize, SMEM_TOTAL);
    cudaFuncSetAttribute(mma_gemm<2>, cudaFuncAttributeMaxDynamicSharedMemorySize, SMEM_TOTAL);
    cudaFuncSetAttribute(mma_gemm<3>, cudaFuncAttributeMaxDynamicSharedMemorySize, SMEM_TOTAL);

    __nv_bfloat16 *xn,*q,*k,*v,*vt,*cx,*pun,*wqT,*wkT,*wvT,*woT;
    float *rsum;
    SYM(xn,  g_xn);   SYM(q,   g_q);   SYM(k,   g_k);  SYM(v, g_v);
    SYM(vt,  g_vt);   SYM(cx,  g_ctx); SYM(pun, g_pun);
    SYM(rsum, g_rowsum);
    SYM(wqT, g_wqT);  SYM(wkT, g_wkT); SYM(wvT, g_wvT); SYM(woT, g_woT);

    const size_t LC = (size_t)LSEQ * CDIM;
    const size_t LL = (size_t)LSEQ * LSEQ;
    const float attn_scale = 1.f / sqrtf((float)CDIM);

    // 1) GroupNorm -> bf16 xn ; zero rowsum
    gn_stats_kernel<<<BATCH * GROUPS, 256>>>(x);
    gn_norm_bf16<<<8192, 256>>>(x, gnw, gnb);
    zero_rowsum_kernel<<<BLTOT/256, 256>>>();

    // 2) transpose weights
    dim3 tw(32, 8);
    dim3 gw(CDIM/32, CDIM/32, 1);
    transpose_f2b<<<gw, tw>>>(wq, wqT, CDIM, CDIM);
    transpose_f2b<<<gw, tw>>>(wk, wkT, CDIM, CDIM);
    transpose_f2b<<<gw, tw>>>(wv, wvT, CDIM, CDIM);
    transpose_f2b<<<gw, tw>>>(wo, woT, CDIM, CDIM);

    // 3) QKV projections
    dim3 grid_qkv(CDIM/BN, BLTOT/BM, 1);
    mma_gemm<1><<<grid_qkv, 512, SMEM_TOTAL>>>(xn, wqT, nullptr, q, nullptr,
        CDIM, CDIM, CDIM, CDIM, 0, 0, 0, 1.f, bq, nullptr);
    mma_gemm<1><<<grid_qkv, 512, SMEM_TOTAL>>>(xn, wkT, nullptr, k, nullptr,
        CDIM, CDIM, CDIM, CDIM, 0, 0, 0, 1.f, bk, nullptr);
    mma_gemm<1><<<grid_qkv, 512, SMEM_TOTAL>>>(xn, wvT, nullptr, v, nullptr,
        CDIM, CDIM, CDIM, CDIM, 0, 0, 0, 1.f, bv, nullptr);

    // 4) V^T
    transpose_b2b<<<dim3(CDIM/32, LSEQ/32, BATCH), tw>>>(v, vt, LSEQ, CDIM, LC, LC);

    // 5) unnormalized P = exp(scale*Q@K^T - SHIFT), accumulate row sums
    dim3 grid_s(LSEQ/BN, LSEQ/BM, BATCH);
    mma_gemm<2><<<grid_s, 512, SMEM_TOTAL>>>(q, k, nullptr, pun, rsum,
        CDIM, CDIM, CDIM, LSEQ, LC, LC, LL, attn_scale, nullptr, nullptr);

    // 6) ctx = (P_un @ V) / rowsum
    dim3 grid_pv(CDIM/BN, LSEQ/BM, BATCH);
    mma_gemm<3><<<grid_pv, 512, SMEM_TOTAL>>>(pun, vt, nullptr, cx, rsum,
        LSEQ, LSEQ, LSEQ, CDIM, LL, LC, LC, 1.f, nullptr, nullptr);

    // 7) out = ctx @ wo^T + bo + residual
    mma_gemm<0><<<grid_qkv, 512, SMEM_TOTAL>>>(cx, woT, out, nullptr, nullptr,
        CDIM, CDIM, CDIM, CDIM, 0, 0, 0, 1.f, bo, x);
}